// round 12
// baseline (speedup 1.0000x reference)
#include <cuda_runtime.h>
#include <cstdint>

#define NNODES  100000
#define HIDDIM  128
#define KIN     500
#define KPAD    512
#define KCH     384
#define ODIM    16
#define MAXE    1600000

// ---------------- device scratch (no allocations allowed) -------------------
static __device__ float    g_h0[(size_t)NNODES * HIDDIM];   // 51.2 MB
static __device__ float    g_h1[(size_t)NNODES * HIDDIM];   // 51.2 MB
static __device__ uint32_t g_Wt[KPAD * HIDDIM];             // W_in tf32 [k=512][n=128]
static __device__ uint32_t g_Ct[2 * KCH * HIDDIM];          // cheb tf32 [l][k=3i+d'][o]
static __device__ float    g_bias[2 * HIDDIM];              // T0 bias per layer
static __device__ int      g_deg[NNODES];
static __device__ int      g_rowStart[NNODES + 1];
static __device__ int      g_cursor[NNODES];
static __device__ int      g_colIdx[MAXE];

// ---------------- helpers ---------------------------------------------------
__device__ __forceinline__ uint32_t f2tf32(float f) {
    uint32_t r;
    asm("cvt.rna.tf32.f32 %0, %1;" : "=r"(r) : "f"(f));
    return r;
}
__device__ __forceinline__ float tanh_fast(float x) {
    float y;
    asm("tanh.approx.f32 %0, %1;" : "=f"(y) : "f"(x));
    return y;
}
__device__ __forceinline__ uint32_t smem_u32(const void* p) {
    uint32_t a;
    asm("{ .reg .u64 t; cvta.to.shared.u64 t, %1; cvt.u32.u64 %0, t; }"
        : "=r"(a) : "l"(p));
    return a;
}
__device__ __forceinline__ void cp16(uint32_t dst, const void* src, int srcBytes) {
    asm volatile("cp.async.ca.shared.global [%0], [%1], 16, %2;"
                 :: "r"(dst), "l"(src), "r"(srcBytes));
}
#define CP_COMMIT() asm volatile("cp.async.commit_group;" ::: "memory")
#define CP_WAIT1()  asm volatile("cp.async.wait_group 1;" ::: "memory")
#define CP_WAIT0()  asm volatile("cp.async.wait_group 0;" ::: "memory")

__device__ __forceinline__ void mma_tf32_16n8k8(float* c, const uint32_t* a,
                                                const uint32_t* b) {
    asm volatile(
        "mma.sync.aligned.m16n8k8.row.col.f32.tf32.tf32.f32 "
        "{%0,%1,%2,%3}, {%4,%5,%6,%7}, {%8,%9}, {%0,%1,%2,%3};"
        : "+f"(c[0]), "+f"(c[1]), "+f"(c[2]), "+f"(c[3])
        : "r"(a[0]), "r"(a[1]), "r"(a[2]), "r"(a[3]), "r"(b[0]), "r"(b[1]));
}
__device__ __forceinline__ void acc4(float4& a, const float4& v) {
    a.x += v.x; a.y += v.y; a.z += v.z; a.w += v.w;
}

// ---------------------------------------------------------------------------
// prep: W_in [500,128] -> g_Wt [512,128] tf32 (zero pad);
//       cheb_coeffs [2,128,128,4] -> g_Ct [l][k=3i+(d-1)][o] tf32 (d=1..3)
// ---------------------------------------------------------------------------
__global__ void prep_kernel(const float* __restrict__ Win,
                            const float* __restrict__ cc) {
    int idx = blockIdx.x * blockDim.x + threadIdx.x;
    if (idx < KPAD * HIDDIM) {
        int k = idx >> 7;
        g_Wt[idx] = (k < KIN) ? f2tf32(Win[idx]) : 0u;
        return;
    }
    idx -= KPAD * HIDDIM;
    if (idx < 2 * KCH * HIDDIM) {
        int l = idx / (KCH * HIDDIM);
        int r = idx - l * (KCH * HIDDIM);
        int k = r >> 7;             // 0..383
        int o = r & 127;
        int i = k / 3, d = k - i * 3 + 1;   // d = 1..3
        g_Ct[idx] = f2tf32(cc[(((l * 128 + i) * 128) + o) * 4 + d]);
    }
}

// bias[l][o] = sum_i cc[l,i,o,0]   (T0 contribution)
__global__ void bias_kernel(const float* __restrict__ cc) {
    int tid = blockIdx.x * blockDim.x + threadIdx.x;
    if (tid >= 2 * HIDDIM) return;
    int l = tid >> 7, o = tid & 127;
    float s = 0.f;
    for (int i = 0; i < 128; i++)
        s += cc[(((l * 128 + i) * 128) + o) * 4];
    g_bias[tid] = s;
}

// ---------------------------------------------------------------------------
// CSR build
// ---------------------------------------------------------------------------
__global__ void zero_deg_kernel(int* __restrict__ deg, int n) {
    int i = blockIdx.x * blockDim.x + threadIdx.x;
    if (i < n) deg[i] = 0;
}
__global__ void count_kernel(const int* __restrict__ ei, int nE,
                             int* __restrict__ deg) {
    int i = blockIdx.x * blockDim.x + threadIdx.x;
    if (i < nE) atomicAdd(&deg[ei[i]], 1);
}
__global__ void __launch_bounds__(1024) scan_kernel(
    const int* __restrict__ deg, int* __restrict__ rowStart,
    int* __restrict__ cursor, int n)
{
    __shared__ int s[1024];
    const int tid = threadIdx.x;
    const int CH = (n + 1023) / 1024;
    const int base = tid * CH;
    int sum = 0;
    for (int i = 0; i < CH; i++) {
        int j = base + i;
        if (j < n) sum += deg[j];
    }
    s[tid] = sum;
    __syncthreads();
    for (int off = 1; off < 1024; off <<= 1) {
        int v = (tid >= off) ? s[tid - off] : 0;
        __syncthreads();
        s[tid] += v;
        __syncthreads();
    }
    int run = (tid == 0) ? 0 : s[tid - 1];
    for (int i = 0; i < CH; i++) {
        int j = base + i;
        if (j < n) {
            rowStart[j] = run;
            cursor[j]   = run;
            run += deg[j];
        }
    }
    if (tid == 1023) rowStart[n] = run;
}
__global__ void fill_kernel(const int* __restrict__ ei, int nE,
                            int* __restrict__ cursor,
                            int* __restrict__ colIdx) {
    int i = blockIdx.x * blockDim.x + threadIdx.x;
    if (i >= nE) return;
    int p = atomicAdd(&cursor[ei[i]], 1);
    colIdx[p] = ei[nE + i];
}

// ---------------------------------------------------------------------------
// spmm via CSR: warp per row, register accumulation (MLP-2).
// ---------------------------------------------------------------------------
__global__ void __launch_bounds__(256) spmm_csr_kernel(
    const int* __restrict__ rowStart, const int* __restrict__ colIdx,
    const float* __restrict__ hin, float* __restrict__ hout, int n)
{
    int w = (blockIdx.x * 256 + threadIdx.x) >> 5;
    if (w >= n) return;
    int lane = threadIdx.x & 31;
    int s = rowStart[w];
    int e = rowStart[w + 1];

    float4 a0 = make_float4(0.f, 0.f, 0.f, 0.f);
    float4 a1 = make_float4(0.f, 0.f, 0.f, 0.f);
    int i = s;
    for (; i + 1 < e; i += 2) {
        int c0 = __ldg(&colIdx[i]);
        int c1 = __ldg(&colIdx[i + 1]);
        float4 v0 = *(const float4*)(hin + (size_t)c0 * HIDDIM + lane * 4);
        float4 v1 = *(const float4*)(hin + (size_t)c1 * HIDDIM + lane * 4);
        acc4(a0, v0); acc4(a1, v1);
    }
    if (i < e) {
        int c0 = __ldg(&colIdx[i]);
        float4 v0 = *(const float4*)(hin + (size_t)c0 * HIDDIM + lane * 4);
        acc4(a0, v0);
    }
    acc4(a0, a1);
    *(float4*)(hout + (size_t)w * HIDDIM + lane * 4) = a0;
}

// ---------------------------------------------------------------------------
// Fused: spmm row aggregation + W_out projection + log_softmax (MLP-2).
// ---------------------------------------------------------------------------
__global__ void __launch_bounds__(256) spmm_out_kernel(
    const int* __restrict__ rowStart, const int* __restrict__ colIdx,
    const float* __restrict__ hin, const float* __restrict__ Wout,
    float* __restrict__ out, int n)
{
    __shared__ float W[HIDDIM * ODIM];
    for (int i = threadIdx.x; i < HIDDIM * ODIM; i += 256) W[i] = Wout[i];
    __syncthreads();

    int w = (blockIdx.x * 256 + threadIdx.x) >> 5;
    if (w >= n) return;
    int lane = threadIdx.x & 31;
    int s = rowStart[w];
    int e = rowStart[w + 1];

    float4 a0 = make_float4(0.f, 0.f, 0.f, 0.f);
    float4 a1 = make_float4(0.f, 0.f, 0.f, 0.f);
    int i = s;
    for (; i + 1 < e; i += 2) {
        int c0 = __ldg(&colIdx[i]);
        int c1 = __ldg(&colIdx[i + 1]);
        float4 v0 = *(const float4*)(hin + (size_t)c0 * HIDDIM + lane * 4);
        float4 v1 = *(const float4*)(hin + (size_t)c1 * HIDDIM + lane * 4);
        acc4(a0, v0); acc4(a1, v1);
    }
    if (i < e) {
        int c0 = __ldg(&colIdx[i]);
        float4 v0 = *(const float4*)(hin + (size_t)c0 * HIDDIM + lane * 4);
        acc4(a0, v0);
    }
    acc4(a0, a1);
    float4 hv = a0;

    int i0 = lane * 4;
    float acc[ODIM];
#pragma unroll
    for (int o = 0; o < ODIM; o++) {
        float t = hv.x * W[(i0 + 0) * ODIM + o];
        t = fmaf(hv.y, W[(i0 + 1) * ODIM + o], t);
        t = fmaf(hv.z, W[(i0 + 2) * ODIM + o], t);
        t = fmaf(hv.w, W[(i0 + 3) * ODIM + o], t);
        acc[o] = t;
    }
#pragma unroll
    for (int off = 16; off > 0; off >>= 1)
#pragma unroll
        for (int o = 0; o < ODIM; o++)
            acc[o] += __shfl_xor_sync(0xffffffffu, acc[o], off);

    float m = acc[0];
#pragma unroll
    for (int o = 1; o < ODIM; o++) m = fmaxf(m, acc[o]);
    float sum = 0.f;
#pragma unroll
    for (int o = 0; o < ODIM; o++) sum += expf(acc[o] - m);
    float lse = m + logf(sum);
    if (lane < ODIM) out[(size_t)w * ODIM + lane] = acc[lane] - lse;
}

// ---------------------------------------------------------------------------
// tf32 mma.sync GEMM, cp.async 2-stage double-buffered pipeline.
//   CHEB=0: Cout = x @ Wt  (K=512, 16 chunks of 32; A+B via cp.async,
//           raw fp32 bits -> mma.tf32, HW truncation)
//   CHEB=1: Cout = basis(tanh(h)) @ Ct + bias (K=384, 16 chunks of 24;
//           B via cp.async, A computed via tanh.approx -> STS)
// 8 warps as 2(m) x 4(n); warp tile 64x32; m16n8k8 atoms.
// ---------------------------------------------------------------------------
#define APITCH 36
#define BPITCH 136
#define ABYTES (128 * APITCH * 4)          // 18432
#define BBYTES (32 * BPITCH * 4)           // 17408
#define GEMM_SMEM (2 * (ABYTES + BBYTES))  // 71680

template <int CHEB>
__global__ void __launch_bounds__(256) gemm_mma(
    const float* __restrict__ A, const uint32_t* __restrict__ B,
    const float* __restrict__ bias, float* __restrict__ Cout, int nRows)
{
    constexpr int KW     = CHEB ? 24 : 32;   // k-cols per chunk
    constexpr int NCH    = 16;
    constexpr int KSTEPS = CHEB ? 3 : 4;
    constexpr int BITER  = CHEB ? 3 : 4;     // B fill iterations

    extern __shared__ char smem[];
    const uint32_t sb = smem_u32(smem);

    const int tid  = threadIdx.x;
    const int wid  = tid >> 5;
    const int lane = tid & 31;
    const int wm = wid >> 2;
    const int wn = wid & 3;
    const int g = lane >> 2;
    const int t = lane & 3;
    const int rowBase = blockIdx.x * 128;

    float acc[4][4][4];
#pragma unroll
    for (int mf = 0; mf < 4; mf++)
#pragma unroll
        for (int nf = 0; nf < 4; nf++)
#pragma unroll
            for (int r = 0; r < 4; r++) acc[mf][nf][r] = 0.f;

    float aH[4];   // CHEB: staged h values (4 regs only)

    // ---- async issue of chunk c into buffer c&1 ----
    auto issue = [&](int c) {
        const int buf = c & 1;
        const uint32_t aBase = sb + buf * ABYTES;
        const uint32_t bBase = sb + 2 * ABYTES + buf * BBYTES;
        if (!CHEB) {
#pragma unroll
            for (int j = 0; j < 4; j++) {
                int pos = tid + j * 256;
                int row = pos >> 3, kq = pos & 7;
                int kk = c * 32 + kq * 4;
                int rg = rowBase + row; if (rg >= nRows) rg = nRows - 1;
                int sbytes = (KIN - kk) * 4;
                sbytes = sbytes < 0 ? 0 : (sbytes > 16 ? 16 : sbytes);
                cp16(aBase + (row * APITCH + kq * 4) * 4,
                     A + (size_t)rg * KIN + kk, sbytes);
            }
        }
#pragma unroll
        for (int j = 0; j < BITER; j++) {
            int pos = tid + j * 256;
            int k = pos >> 5, nq = pos & 31;
            cp16(bBase + (k * BPITCH + nq * 4) * 4,
                 B + (size_t)(c * KW + k) * HIDDIM + nq * 4, 16);
        }
        CP_COMMIT();
    };
    auto ldgA = [&](int c) {
        if (CHEB) {
#pragma unroll
            for (int j = 0; j < 4; j++) {
                int pos = tid + j * 256;
                int row = pos >> 3, il = pos & 7;
                int rg = rowBase + row; if (rg >= nRows) rg = nRows - 1;
                aH[j] = __ldg(&A[(size_t)rg * HIDDIM + c * 8 + il]);
            }
        }
    };

    issue(0);
    ldgA(0);

    for (int c = 0; c < NCH; c++) {
        const int buf = c & 1;
        uint32_t* As = (uint32_t*)(smem + buf * ABYTES);
        uint32_t* Bs = (uint32_t*)(smem + 2 * ABYTES + buf * BBYTES);

        if (CHEB) {
            // compute basis for chunk c, store fp32 bits (HW truncates)
#pragma unroll
            for (int j = 0; j < 4; j++) {
                int pos = tid + j * 256;
                int row = pos >> 3, il = pos & 7;
                float tv = tanh_fast(aH[j]);
                float T2 = fmaf(2.f * tv, tv, -1.f);
                float T3 = fmaf(2.f * tv, T2, -tv);
                uint32_t* p = &As[row * APITCH + il * 3];
                p[0] = __float_as_uint(tv);
                p[1] = __float_as_uint(T2);
                p[2] = __float_as_uint(T3);
            }
        }

        if (c + 1 < NCH) {
            issue(c + 1);      // into buffer (c+1)&1 — free since MMA c-1 synced
            ldgA(c + 1);       // h loads overlap wait + MMA below
            CP_WAIT1();        // chunk c's group complete
        } else {
            CP_WAIT0();
        }
        __syncthreads();

        // ---- KSTEPS x m16n8k8 ----
#pragma unroll
        for (int ks = 0; ks < KSTEPS; ks++) {
            const int kk = ks * 8;
            uint32_t a[4][4], b[4][2];
#pragma unroll
            for (int mf = 0; mf < 4; mf++) {
                int mb = wm * 64 + mf * 16;
                a[mf][0] = As[(mb + g)     * APITCH + kk + t];
                a[mf][1] = As[(mb + g + 8) * APITCH + kk + t];
                a[mf][2] = As[(mb + g)     * APITCH + kk + t + 4];
                a[mf][3] = As[(mb + g + 8) * APITCH + kk + t + 4];
            }
#pragma unroll
            for (int nf = 0; nf < 4; nf++) {
                int nb = wn * 32 + nf * 8;
                b[nf][0] = Bs[(kk + t)     * BPITCH + nb + g];
                b[nf][1] = Bs[(kk + t + 4) * BPITCH + nb + g];
            }
#pragma unroll
            for (int mf = 0; mf < 4; mf++)
#pragma unroll
                for (int nf = 0; nf < 4; nf++)
                    mma_tf32_16n8k8(acc[mf][nf], a[mf], b[nf]);
        }
        __syncthreads();       // MMA reads done before this buffer is refilled
    }

    // ---- epilogue (bias only in CHEB mode) ----
#pragma unroll
    for (int mf = 0; mf < 4; mf++) {
        int row0 = rowBase + wm * 64 + mf * 16 + g;
#pragma unroll
        for (int nf = 0; nf < 4; nf++) {
            int col = wn * 32 + nf * 8 + t * 2;
            float b0 = 0.f, b1 = 0.f;
            if (CHEB) { b0 = __ldg(&bias[col]); b1 = __ldg(&bias[col + 1]); }
            if (row0 < nRows)
                *(float2*)&Cout[(size_t)row0 * HIDDIM + col] =
                    make_float2(acc[mf][nf][0] + b0, acc[mf][nf][1] + b1);
            if (row0 + 8 < nRows)
                *(float2*)&Cout[(size_t)(row0 + 8) * HIDDIM + col] =
                    make_float2(acc[mf][nf][2] + b0, acc[mf][nf][3] + b1);
        }
    }
}

// ---------------------------------------------------------------------------
extern "C" void kernel_launch(void* const* d_in, const int* in_sizes, int n_in,
                              void* d_out, int out_size)
{
    const float* x    = (const float*)d_in[0];
    const int*   ei   = (const int*)d_in[1];
    const float* Win  = (const float*)d_in[2];
    const float* cc   = (const float*)d_in[3];
    const float* Wout = (const float*)d_in[4];
    float* out = (float*)d_out;

    const int nE    = in_sizes[1] / 2;
    const int nRows = NNODES;

    float *h0, *h1, *bias;
    uint32_t *Wt, *Ct;
    int *deg, *rowStart, *cursor, *colIdx;
    cudaGetSymbolAddress((void**)&h0, g_h0);
    cudaGetSymbolAddress((void**)&h1, g_h1);
    cudaGetSymbolAddress((void**)&Wt, g_Wt);
    cudaGetSymbolAddress((void**)&Ct, g_Ct);
    cudaGetSymbolAddress((void**)&bias, g_bias);
    cudaGetSymbolAddress((void**)&deg,      g_deg);
    cudaGetSymbolAddress((void**)&rowStart, g_rowStart);
    cudaGetSymbolAddress((void**)&cursor,   g_cursor);
    cudaGetSymbolAddress((void**)&colIdx,   g_colIdx);

    static cudaStream_t s2 = nullptr;
    static cudaEvent_t evFork = nullptr, evJoin = nullptr;
    static bool setupDone = false;
    if (!setupDone) {
        cudaFuncSetAttribute(gemm_mma<0>,
            cudaFuncAttributeMaxDynamicSharedMemorySize, GEMM_SMEM);
        cudaFuncSetAttribute(gemm_mma<1>,
            cudaFuncAttributeMaxDynamicSharedMemorySize, GEMM_SMEM);
        cudaStreamCreateWithFlags(&s2, cudaStreamNonBlocking);
        cudaEventCreateWithFlags(&evFork, cudaEventDisableTiming);
        cudaEventCreateWithFlags(&evJoin, cudaEventDisableTiming);
        setupDone = true;
    }

    const int gemmBlocks = (nRows + 127) / 128;          // 782
    const int eBlocks    = (nE + 255) / 256;
    const int spmmBlocks = (nRows * 32 + 255) / 256;
    const int prepElems  = KPAD * HIDDIM + 2 * KCH * HIDDIM;

    // ---- fork: CSR build + bias on s2, concurrent with prep + gemm0 ----
    cudaEventRecord(evFork, 0);
    cudaStreamWaitEvent(s2, evFork, 0);
    zero_deg_kernel<<<(nRows + 255) / 256, 256, 0, s2>>>(deg, nRows);
    count_kernel<<<eBlocks, 256, 0, s2>>>(ei, nE, deg);
    scan_kernel<<<1, 1024, 0, s2>>>(deg, rowStart, cursor, nRows);
    fill_kernel<<<eBlocks, 256, 0, s2>>>(ei, nE, cursor, colIdx);
    bias_kernel<<<1, 256, 0, s2>>>(cc);
    cudaEventRecord(evJoin, s2);

    // ---- main stream: prep + gemm0 (independent of CSR) ----
    prep_kernel<<<(prepElems + 255) / 256, 256>>>(Win, cc);
    gemm_mma<0><<<gemmBlocks, 256, GEMM_SMEM>>>(x, Wt, nullptr, h0, nRows);

    // ---- join: first spmm needs CSR ----
    cudaStreamWaitEvent(0, evJoin, 0);

    // h1 = A h0
    spmm_csr_kernel<<<spmmBlocks, 256>>>(rowStart, colIdx, h0, h1, nRows);
    // h0 = cheb(h1; C0)
    gemm_mma<1><<<gemmBlocks, 256, GEMM_SMEM>>>(h1, Ct, bias, h0, nRows);
    spmm_csr_kernel<<<spmmBlocks, 256>>>(rowStart, colIdx, h0, h1, nRows);
    // h0 = cheb(h1; C1)
    gemm_mma<1><<<gemmBlocks, 256, GEMM_SMEM>>>(h1, Ct + KCH * HIDDIM,
                                                bias + HIDDIM, h0, nRows);
    // fused: spmm + W_out + log_softmax
    spmm_out_kernel<<<spmmBlocks, 256>>>(rowStart, colIdx, h0, Wout, out, nRows);
}

// round 13
// speedup vs baseline: 1.0587x; 1.0587x over previous
#include <cuda_runtime.h>
#include <cstdint>

#define NNODES  100000
#define HIDDIM  128
#define KIN     500
#define KPAD    512
#define KCH     384
#define ODIM    16
#define MAXE    1600000

// ---------------- device scratch (no allocations allowed) -------------------
static __device__ float    g_h0[(size_t)NNODES * HIDDIM];   // 51.2 MB
static __device__ float    g_h1[(size_t)NNODES * HIDDIM];   // 51.2 MB
static __device__ uint32_t g_Wt[KPAD * HIDDIM];             // W_in tf32 [k=512][n=128]
static __device__ uint32_t g_Ct[2 * KCH * HIDDIM];          // cheb tf32 [l][k=3i+d'][o]
static __device__ float    g_bias[2 * HIDDIM];              // T0 bias per layer
static __device__ int      g_deg[NNODES];
static __device__ int      g_rowStart[NNODES + 1];
static __device__ int      g_cursor[NNODES];
static __device__ int      g_colIdx[MAXE];

// ---------------- helpers ---------------------------------------------------
__device__ __forceinline__ uint32_t f2tf32(float f) {
    uint32_t r;
    asm("cvt.rna.tf32.f32 %0, %1;" : "=r"(r) : "f"(f));
    return r;
}
__device__ __forceinline__ float tanh_fast(float x) {
    float y;
    asm("tanh.approx.f32 %0, %1;" : "=f"(y) : "f"(x));
    return y;
}
__device__ __forceinline__ uint32_t smem_u32(const void* p) {
    uint32_t a;
    asm("{ .reg .u64 t; cvta.to.shared.u64 t, %1; cvt.u32.u64 %0, t; }"
        : "=r"(a) : "l"(p));
    return a;
}
__device__ __forceinline__ void cp16(uint32_t dst, const void* src, int srcBytes) {
    asm volatile("cp.async.ca.shared.global [%0], [%1], 16, %2;"
                 :: "r"(dst), "l"(src), "r"(srcBytes));
}
#define CP_COMMIT() asm volatile("cp.async.commit_group;" ::: "memory")
#define CP_WAIT1()  asm volatile("cp.async.wait_group 1;" ::: "memory")
#define CP_WAIT0()  asm volatile("cp.async.wait_group 0;" ::: "memory")

__device__ __forceinline__ void mma_tf32_16n8k8(float* c, const uint32_t* a,
                                                const uint32_t* b) {
    asm volatile(
        "mma.sync.aligned.m16n8k8.row.col.f32.tf32.tf32.f32 "
        "{%0,%1,%2,%3}, {%4,%5,%6,%7}, {%8,%9}, {%0,%1,%2,%3};"
        : "+f"(c[0]), "+f"(c[1]), "+f"(c[2]), "+f"(c[3])
        : "r"(a[0]), "r"(a[1]), "r"(a[2]), "r"(a[3]), "r"(b[0]), "r"(b[1]));
}
__device__ __forceinline__ void acc4(float4& a, const float4& v) {
    a.x += v.x; a.y += v.y; a.z += v.z; a.w += v.w;
}

// ---------------------------------------------------------------------------
// prep: W_in [500,128] -> g_Wt [512,128] tf32 (zero pad);
//       cheb_coeffs [2,128,128,4] -> g_Ct [l][k=3i+(d-1)][o] tf32 (d=1..3)
// ---------------------------------------------------------------------------
__global__ void prep_kernel(const float* __restrict__ Win,
                            const float* __restrict__ cc) {
    int idx = blockIdx.x * blockDim.x + threadIdx.x;
    if (idx < KPAD * HIDDIM) {
        int k = idx >> 7;
        g_Wt[idx] = (k < KIN) ? f2tf32(Win[idx]) : 0u;
        return;
    }
    idx -= KPAD * HIDDIM;
    if (idx < 2 * KCH * HIDDIM) {
        int l = idx / (KCH * HIDDIM);
        int r = idx - l * (KCH * HIDDIM);
        int k = r >> 7;             // 0..383
        int o = r & 127;
        int i = k / 3, d = k - i * 3 + 1;   // d = 1..3
        g_Ct[idx] = f2tf32(cc[(((l * 128 + i) * 128) + o) * 4 + d]);
    }
}

// bias[l][o] = sum_i cc[l,i,o,0]   (T0 contribution)
__global__ void bias_kernel(const float* __restrict__ cc) {
    int tid = blockIdx.x * blockDim.x + threadIdx.x;
    if (tid >= 2 * HIDDIM) return;
    int l = tid >> 7, o = tid & 127;
    float s = 0.f;
    for (int i = 0; i < 128; i++)
        s += cc[(((l * 128 + i) * 128) + o) * 4];
    g_bias[tid] = s;
}

// ---------------------------------------------------------------------------
// CSR build
// ---------------------------------------------------------------------------
__global__ void zero_deg_kernel(int* __restrict__ deg, int n) {
    int i = blockIdx.x * blockDim.x + threadIdx.x;
    if (i < n) deg[i] = 0;
}
__global__ void count_kernel(const int* __restrict__ ei, int nE,
                             int* __restrict__ deg) {
    int i = blockIdx.x * blockDim.x + threadIdx.x;
    if (i < nE) atomicAdd(&deg[ei[i]], 1);
}
__global__ void __launch_bounds__(1024) scan_kernel(
    const int* __restrict__ deg, int* __restrict__ rowStart,
    int* __restrict__ cursor, int n)
{
    __shared__ int s[1024];
    const int tid = threadIdx.x;
    const int CH = (n + 1023) / 1024;
    const int base = tid * CH;
    int sum = 0;
    for (int i = 0; i < CH; i++) {
        int j = base + i;
        if (j < n) sum += deg[j];
    }
    s[tid] = sum;
    __syncthreads();
    for (int off = 1; off < 1024; off <<= 1) {
        int v = (tid >= off) ? s[tid - off] : 0;
        __syncthreads();
        s[tid] += v;
        __syncthreads();
    }
    int run = (tid == 0) ? 0 : s[tid - 1];
    for (int i = 0; i < CH; i++) {
        int j = base + i;
        if (j < n) {
            rowStart[j] = run;
            cursor[j]   = run;
            run += deg[j];
        }
    }
    if (tid == 1023) rowStart[n] = run;
}
__global__ void fill_kernel(const int* __restrict__ ei, int nE,
                            int* __restrict__ cursor,
                            int* __restrict__ colIdx) {
    int i = blockIdx.x * blockDim.x + threadIdx.x;
    if (i >= nE) return;
    int p = atomicAdd(&cursor[ei[i]], 1);
    colIdx[p] = ei[nE + i];
}

// ---------------------------------------------------------------------------
// spmm via CSR: warp per row, register accumulation (MLP-2).
// ---------------------------------------------------------------------------
__global__ void __launch_bounds__(256) spmm_csr_kernel(
    const int* __restrict__ rowStart, const int* __restrict__ colIdx,
    const float* __restrict__ hin, float* __restrict__ hout, int n)
{
    int w = (blockIdx.x * 256 + threadIdx.x) >> 5;
    if (w >= n) return;
    int lane = threadIdx.x & 31;
    int s = rowStart[w];
    int e = rowStart[w + 1];

    float4 a0 = make_float4(0.f, 0.f, 0.f, 0.f);
    float4 a1 = make_float4(0.f, 0.f, 0.f, 0.f);
    int i = s;
    for (; i + 1 < e; i += 2) {
        int c0 = __ldg(&colIdx[i]);
        int c1 = __ldg(&colIdx[i + 1]);
        float4 v0 = *(const float4*)(hin + (size_t)c0 * HIDDIM + lane * 4);
        float4 v1 = *(const float4*)(hin + (size_t)c1 * HIDDIM + lane * 4);
        acc4(a0, v0); acc4(a1, v1);
    }
    if (i < e) {
        int c0 = __ldg(&colIdx[i]);
        float4 v0 = *(const float4*)(hin + (size_t)c0 * HIDDIM + lane * 4);
        acc4(a0, v0);
    }
    acc4(a0, a1);
    *(float4*)(hout + (size_t)w * HIDDIM + lane * 4) = a0;
}

// ---------------------------------------------------------------------------
// Fused: spmm row aggregation + W_out projection + log_softmax (MLP-2).
// ---------------------------------------------------------------------------
__global__ void __launch_bounds__(256) spmm_out_kernel(
    const int* __restrict__ rowStart, const int* __restrict__ colIdx,
    const float* __restrict__ hin, const float* __restrict__ Wout,
    float* __restrict__ out, int n)
{
    __shared__ float W[HIDDIM * ODIM];
    for (int i = threadIdx.x; i < HIDDIM * ODIM; i += 256) W[i] = Wout[i];
    __syncthreads();

    int w = (blockIdx.x * 256 + threadIdx.x) >> 5;
    if (w >= n) return;
    int lane = threadIdx.x & 31;
    int s = rowStart[w];
    int e = rowStart[w + 1];

    float4 a0 = make_float4(0.f, 0.f, 0.f, 0.f);
    float4 a1 = make_float4(0.f, 0.f, 0.f, 0.f);
    int i = s;
    for (; i + 1 < e; i += 2) {
        int c0 = __ldg(&colIdx[i]);
        int c1 = __ldg(&colIdx[i + 1]);
        float4 v0 = *(const float4*)(hin + (size_t)c0 * HIDDIM + lane * 4);
        float4 v1 = *(const float4*)(hin + (size_t)c1 * HIDDIM + lane * 4);
        acc4(a0, v0); acc4(a1, v1);
    }
    if (i < e) {
        int c0 = __ldg(&colIdx[i]);
        float4 v0 = *(const float4*)(hin + (size_t)c0 * HIDDIM + lane * 4);
        acc4(a0, v0);
    }
    acc4(a0, a1);
    float4 hv = a0;

    int i0 = lane * 4;
    float acc[ODIM];
#pragma unroll
    for (int o = 0; o < ODIM; o++) {
        float t = hv.x * W[(i0 + 0) * ODIM + o];
        t = fmaf(hv.y, W[(i0 + 1) * ODIM + o], t);
        t = fmaf(hv.z, W[(i0 + 2) * ODIM + o], t);
        t = fmaf(hv.w, W[(i0 + 3) * ODIM + o], t);
        acc[o] = t;
    }
#pragma unroll
    for (int off = 16; off > 0; off >>= 1)
#pragma unroll
        for (int o = 0; o < ODIM; o++)
            acc[o] += __shfl_xor_sync(0xffffffffu, acc[o], off);

    float m = acc[0];
#pragma unroll
    for (int o = 1; o < ODIM; o++) m = fmaxf(m, acc[o]);
    float sum = 0.f;
#pragma unroll
    for (int o = 0; o < ODIM; o++) sum += expf(acc[o] - m);
    float lse = m + logf(sum);
    if (lane < ODIM) out[(size_t)w * ODIM + lane] = acc[lane] - lse;
}

// ---------------------------------------------------------------------------
// tf32 mma.sync GEMM, cp.async 2-stage double-buffered pipeline.
//   CHEB=0: Cout = x @ Wt  (K=512, 16 chunks of 32; A+B via cp.async,
//           raw fp32 bits -> mma.tf32, HW truncation)
//   CHEB=1: Cout = basis(tanh(h)) @ Ct + bias (K=384, 16 chunks of 24;
//           B via cp.async, A computed via tanh.approx -> STS)
// 8 warps as 2(m) x 4(n); warp tile 64x32; m16n8k8 atoms.
// ---------------------------------------------------------------------------
#define APITCH 36
#define BPITCH 136
#define ABYTES (128 * APITCH * 4)          // 18432
#define BBYTES (32 * BPITCH * 4)           // 17408
#define GEMM_SMEM (2 * (ABYTES + BBYTES))  // 71680

template <int CHEB>
__global__ void __launch_bounds__(256) gemm_mma(
    const float* __restrict__ A, const uint32_t* __restrict__ B,
    const float* __restrict__ bias, float* __restrict__ Cout, int nRows)
{
    constexpr int KW     = CHEB ? 24 : 32;   // k-cols per chunk
    constexpr int NCH    = 16;
    constexpr int KSTEPS = CHEB ? 3 : 4;
    constexpr int BITER  = CHEB ? 3 : 4;     // B fill iterations

    extern __shared__ char smem[];
    const uint32_t sb = smem_u32(smem);

    const int tid  = threadIdx.x;
    const int wid  = tid >> 5;
    const int lane = tid & 31;
    const int wm = wid >> 2;
    const int wn = wid & 3;
    const int g = lane >> 2;
    const int t = lane & 3;
    const int rowBase = blockIdx.x * 128;

    float acc[4][4][4];
#pragma unroll
    for (int mf = 0; mf < 4; mf++)
#pragma unroll
        for (int nf = 0; nf < 4; nf++)
#pragma unroll
            for (int r = 0; r < 4; r++) acc[mf][nf][r] = 0.f;

    float aH[4];   // CHEB: staged h values (4 regs only)

    // ---- async issue of chunk c into buffer c&1 ----
    auto issue = [&](int c) {
        const int buf = c & 1;
        const uint32_t aBase = sb + buf * ABYTES;
        const uint32_t bBase = sb + 2 * ABYTES + buf * BBYTES;
        if (!CHEB) {
#pragma unroll
            for (int j = 0; j < 4; j++) {
                int pos = tid + j * 256;
                int row = pos >> 3, kq = pos & 7;
                int kk = c * 32 + kq * 4;
                int rg = rowBase + row; if (rg >= nRows) rg = nRows - 1;
                int sbytes = (KIN - kk) * 4;
                sbytes = sbytes < 0 ? 0 : (sbytes > 16 ? 16 : sbytes);
                cp16(aBase + (row * APITCH + kq * 4) * 4,
                     A + (size_t)rg * KIN + kk, sbytes);
            }
        }
#pragma unroll
        for (int j = 0; j < BITER; j++) {
            int pos = tid + j * 256;
            int k = pos >> 5, nq = pos & 31;
            cp16(bBase + (k * BPITCH + nq * 4) * 4,
                 B + (size_t)(c * KW + k) * HIDDIM + nq * 4, 16);
        }
        CP_COMMIT();
    };
    auto ldgA = [&](int c) {
        if (CHEB) {
#pragma unroll
            for (int j = 0; j < 4; j++) {
                int pos = tid + j * 256;
                int row = pos >> 3, il = pos & 7;
                int rg = rowBase + row; if (rg >= nRows) rg = nRows - 1;
                aH[j] = __ldg(&A[(size_t)rg * HIDDIM + c * 8 + il]);
            }
        }
    };

    issue(0);
    ldgA(0);

    for (int c = 0; c < NCH; c++) {
        const int buf = c & 1;
        uint32_t* As = (uint32_t*)(smem + buf * ABYTES);
        uint32_t* Bs = (uint32_t*)(smem + 2 * ABYTES + buf * BBYTES);

        if (CHEB) {
            // compute basis for chunk c, store fp32 bits (HW truncates)
#pragma unroll
            for (int j = 0; j < 4; j++) {
                int pos = tid + j * 256;
                int row = pos >> 3, il = pos & 7;
                float tv = tanh_fast(aH[j]);
                float T2 = fmaf(2.f * tv, tv, -1.f);
                float T3 = fmaf(2.f * tv, T2, -tv);
                uint32_t* p = &As[row * APITCH + il * 3];
                p[0] = __float_as_uint(tv);
                p[1] = __float_as_uint(T2);
                p[2] = __float_as_uint(T3);
            }
        }

        if (c + 1 < NCH) {
            issue(c + 1);      // into buffer (c+1)&1 — free since MMA c-1 synced
            ldgA(c + 1);       // h loads overlap wait + MMA below
            CP_WAIT1();        // chunk c's group complete
        } else {
            CP_WAIT0();
        }
        __syncthreads();

        // ---- KSTEPS x m16n8k8 ----
#pragma unroll
        for (int ks = 0; ks < KSTEPS; ks++) {
            const int kk = ks * 8;
            uint32_t a[4][4], b[4][2];
#pragma unroll
            for (int mf = 0; mf < 4; mf++) {
                int mb = wm * 64 + mf * 16;
                a[mf][0] = As[(mb + g)     * APITCH + kk + t];
                a[mf][1] = As[(mb + g + 8) * APITCH + kk + t];
                a[mf][2] = As[(mb + g)     * APITCH + kk + t + 4];
                a[mf][3] = As[(mb + g + 8) * APITCH + kk + t + 4];
            }
#pragma unroll
            for (int nf = 0; nf < 4; nf++) {
                int nb = wn * 32 + nf * 8;
                b[nf][0] = Bs[(kk + t)     * BPITCH + nb + g];
                b[nf][1] = Bs[(kk + t + 4) * BPITCH + nb + g];
            }
#pragma unroll
            for (int mf = 0; mf < 4; mf++)
#pragma unroll
                for (int nf = 0; nf < 4; nf++)
                    mma_tf32_16n8k8(acc[mf][nf], a[mf], b[nf]);
        }
        __syncthreads();       // MMA reads done before this buffer is refilled
    }

    // ---- epilogue (bias only in CHEB mode) ----
#pragma unroll
    for (int mf = 0; mf < 4; mf++) {
        int row0 = rowBase + wm * 64 + mf * 16 + g;
#pragma unroll
        for (int nf = 0; nf < 4; nf++) {
            int col = wn * 32 + nf * 8 + t * 2;
            float b0 = 0.f, b1 = 0.f;
            if (CHEB) { b0 = __ldg(&bias[col]); b1 = __ldg(&bias[col + 1]); }
            if (row0 < nRows)
                *(float2*)&Cout[(size_t)row0 * HIDDIM + col] =
                    make_float2(acc[mf][nf][0] + b0, acc[mf][nf][1] + b1);
            if (row0 + 8 < nRows)
                *(float2*)&Cout[(size_t)(row0 + 8) * HIDDIM + col] =
                    make_float2(acc[mf][nf][2] + b0, acc[mf][nf][3] + b1);
        }
    }
}

// ---------------------------------------------------------------------------
extern "C" void kernel_launch(void* const* d_in, const int* in_sizes, int n_in,
                              void* d_out, int out_size)
{
    const float* x    = (const float*)d_in[0];
    const int*   ei   = (const int*)d_in[1];
    const float* Win  = (const float*)d_in[2];
    const float* cc   = (const float*)d_in[3];
    const float* Wout = (const float*)d_in[4];
    float* out = (float*)d_out;

    const int nE    = in_sizes[1] / 2;
    const int nRows = NNODES;

    float *h0, *h1, *bias;
    uint32_t *Wt, *Ct;
    int *deg, *rowStart, *cursor, *colIdx;
    cudaGetSymbolAddress((void**)&h0, g_h0);
    cudaGetSymbolAddress((void**)&h1, g_h1);
    cudaGetSymbolAddress((void**)&Wt, g_Wt);
    cudaGetSymbolAddress((void**)&Ct, g_Ct);
    cudaGetSymbolAddress((void**)&bias, g_bias);
    cudaGetSymbolAddress((void**)&deg,      g_deg);
    cudaGetSymbolAddress((void**)&rowStart, g_rowStart);
    cudaGetSymbolAddress((void**)&cursor,   g_cursor);
    cudaGetSymbolAddress((void**)&colIdx,   g_colIdx);

    static bool attrDone = false;
    if (!attrDone) {
        cudaFuncSetAttribute(gemm_mma<0>,
            cudaFuncAttributeMaxDynamicSharedMemorySize, GEMM_SMEM);
        cudaFuncSetAttribute(gemm_mma<1>,
            cudaFuncAttributeMaxDynamicSharedMemorySize, GEMM_SMEM);
        attrDone = true;
    }

    const int gemmBlocks = (nRows + 127) / 128;          // 782
    const int eBlocks    = (nE + 255) / 256;
    const int spmmBlocks = (nRows * 32 + 255) / 256;
    const int prepElems  = KPAD * HIDDIM + 2 * KCH * HIDDIM;

    // Single stream; gemm_mma<0> at profiled position 4.
    zero_deg_kernel<<<(nRows + 255) / 256, 256>>>(deg, nRows);          // 1
    count_kernel<<<eBlocks, 256>>>(ei, nE, deg);                        // 2
    prep_kernel<<<(prepElems + 255) / 256, 256>>>(Win, cc);             // 3
    gemm_mma<0><<<gemmBlocks, 256, GEMM_SMEM>>>(x, Wt, nullptr, h0, nRows); // 4
    scan_kernel<<<1, 1024>>>(deg, rowStart, cursor, nRows);             // 5
    fill_kernel<<<eBlocks, 256>>>(ei, nE, cursor, colIdx);              // 6
    bias_kernel<<<1, 256>>>(cc);                                        // 7

    // h1 = A h0
    spmm_csr_kernel<<<spmmBlocks, 256>>>(rowStart, colIdx, h0, h1, nRows);
    // h0 = cheb(h1; C0)
    gemm_mma<1><<<gemmBlocks, 256, GEMM_SMEM>>>(h1, Ct, bias, h0, nRows);
    spmm_csr_kernel<<<spmmBlocks, 256>>>(rowStart, colIdx, h0, h1, nRows);
    // h0 = cheb(h1; C1)
    gemm_mma<1><<<gemmBlocks, 256, GEMM_SMEM>>>(h1, Ct + KCH * HIDDIM,
                                                bias + HIDDIM, h0, nRows);
    // fused: spmm + W_out + log_softmax
    spmm_out_kernel<<<spmmBlocks, 256>>>(rowStart, colIdx, h0, Wout, out, nRows);
}

// round 14
// speedup vs baseline: 1.1102x; 1.0486x over previous
#include <cuda_runtime.h>
#include <cuda_fp16.h>
#include <cstdint>

#define NNODES  100000
#define HIDDIM  128
#define KIN     500
#define KPAD    512
#define KCH     384
#define ODIM    16
#define MAXE    1600000

// ---------------- device scratch (no allocations allowed) -------------------
static __device__ __half   g_h0[(size_t)NNODES * HIDDIM];   // 25.6 MB (fp16)
static __device__ __half   g_h1[(size_t)NNODES * HIDDIM];   // 25.6 MB (fp16)
static __device__ uint32_t g_Wt[KPAD * HIDDIM];             // W_in tf32 [k=512][n=128]
static __device__ uint32_t g_Ct[2 * KCH * HIDDIM];          // cheb tf32 [l][k=3i+d'][o]
static __device__ float    g_bias[2 * HIDDIM];              // T0 bias per layer
static __device__ int      g_deg[NNODES];
static __device__ int      g_rowStart[NNODES + 1];
static __device__ int      g_cursor[NNODES];
static __device__ int      g_colIdx[MAXE];

// ---------------- helpers ---------------------------------------------------
__device__ __forceinline__ uint32_t f2tf32(float f) {
    uint32_t r;
    asm("cvt.rna.tf32.f32 %0, %1;" : "=r"(r) : "f"(f));
    return r;
}
__device__ __forceinline__ float tanh_fast(float x) {
    float y;
    asm("tanh.approx.f32 %0, %1;" : "=f"(y) : "f"(x));
    return y;
}
__device__ __forceinline__ uint32_t smem_u32(const void* p) {
    uint32_t a;
    asm("{ .reg .u64 t; cvta.to.shared.u64 t, %1; cvt.u32.u64 %0, t; }"
        : "=r"(a) : "l"(p));
    return a;
}
__device__ __forceinline__ void cp16(uint32_t dst, const void* src, int srcBytes) {
    asm volatile("cp.async.ca.shared.global [%0], [%1], 16, %2;"
                 :: "r"(dst), "l"(src), "r"(srcBytes));
}
#define CP_COMMIT() asm volatile("cp.async.commit_group;" ::: "memory")
#define CP_WAIT1()  asm volatile("cp.async.wait_group 1;" ::: "memory")
#define CP_WAIT0()  asm volatile("cp.async.wait_group 0;" ::: "memory")

__device__ __forceinline__ void mma_tf32_16n8k8(float* c, const uint32_t* a,
                                                const uint32_t* b) {
    asm volatile(
        "mma.sync.aligned.m16n8k8.row.col.f32.tf32.tf32.f32 "
        "{%0,%1,%2,%3}, {%4,%5,%6,%7}, {%8,%9}, {%0,%1,%2,%3};"
        : "+f"(c[0]), "+f"(c[1]), "+f"(c[2]), "+f"(c[3])
        : "r"(a[0]), "r"(a[1]), "r"(a[2]), "r"(a[3]), "r"(b[0]), "r"(b[1]));
}
__device__ __forceinline__ void acc4(float4& a, const float4& v) {
    a.x += v.x; a.y += v.y; a.z += v.z; a.w += v.w;
}
// load 4 halves (8B) -> float4
__device__ __forceinline__ float4 ldh4(const __half* p) {
    uint2 u = *(const uint2*)p;
    float2 f0 = __half22float2(*(__half2*)&u.x);
    float2 f1 = __half22float2(*(__half2*)&u.y);
    return make_float4(f0.x, f0.y, f1.x, f1.y);
}
// store float4 -> 4 halves (8B)
__device__ __forceinline__ void sth4(__half* p, float4 v) {
    __half2 a = __floats2half2_rn(v.x, v.y);
    __half2 b = __floats2half2_rn(v.z, v.w);
    uint2 u;
    u.x = *(uint32_t*)&a;
    u.y = *(uint32_t*)&b;
    *(uint2*)p = u;
}

// ---------------------------------------------------------------------------
// prep: W_in [500,128] -> g_Wt [512,128] tf32 (zero pad);
//       cheb_coeffs [2,128,128,4] -> g_Ct [l][k=3i+(d-1)][o] tf32 (d=1..3)
// ---------------------------------------------------------------------------
__global__ void prep_kernel(const float* __restrict__ Win,
                            const float* __restrict__ cc) {
    int idx = blockIdx.x * blockDim.x + threadIdx.x;
    if (idx < KPAD * HIDDIM) {
        int k = idx >> 7;
        g_Wt[idx] = (k < KIN) ? f2tf32(Win[idx]) : 0u;
        return;
    }
    idx -= KPAD * HIDDIM;
    if (idx < 2 * KCH * HIDDIM) {
        int l = idx / (KCH * HIDDIM);
        int r = idx - l * (KCH * HIDDIM);
        int k = r >> 7;             // 0..383
        int o = r & 127;
        int i = k / 3, d = k - i * 3 + 1;   // d = 1..3
        g_Ct[idx] = f2tf32(cc[(((l * 128 + i) * 128) + o) * 4 + d]);
    }
}

// bias[l][o] = sum_i cc[l,i,o,0]   (T0 contribution)
__global__ void bias_kernel(const float* __restrict__ cc) {
    int tid = blockIdx.x * blockDim.x + threadIdx.x;
    if (tid >= 2 * HIDDIM) return;
    int l = tid >> 7, o = tid & 127;
    float s = 0.f;
    for (int i = 0; i < 128; i++)
        s += cc[(((l * 128 + i) * 128) + o) * 4];
    g_bias[tid] = s;
}

// ---------------------------------------------------------------------------
// CSR build
// ---------------------------------------------------------------------------
__global__ void zero_deg_kernel(int* __restrict__ deg, int n) {
    int i = blockIdx.x * blockDim.x + threadIdx.x;
    if (i < n) deg[i] = 0;
}
__global__ void count_kernel(const int* __restrict__ ei, int nE,
                             int* __restrict__ deg) {
    int i = blockIdx.x * blockDim.x + threadIdx.x;
    if (i < nE) atomicAdd(&deg[ei[i]], 1);
}
__global__ void __launch_bounds__(1024) scan_kernel(
    const int* __restrict__ deg, int* __restrict__ rowStart,
    int* __restrict__ cursor, int n)
{
    __shared__ int s[1024];
    const int tid = threadIdx.x;
    const int CH = (n + 1023) / 1024;
    const int base = tid * CH;
    int sum = 0;
    for (int i = 0; i < CH; i++) {
        int j = base + i;
        if (j < n) sum += deg[j];
    }
    s[tid] = sum;
    __syncthreads();
    for (int off = 1; off < 1024; off <<= 1) {
        int v = (tid >= off) ? s[tid - off] : 0;
        __syncthreads();
        s[tid] += v;
        __syncthreads();
    }
    int run = (tid == 0) ? 0 : s[tid - 1];
    for (int i = 0; i < CH; i++) {
        int j = base + i;
        if (j < n) {
            rowStart[j] = run;
            cursor[j]   = run;
            run += deg[j];
        }
    }
    if (tid == 1023) rowStart[n] = run;
}
__global__ void fill_kernel(const int* __restrict__ ei, int nE,
                            int* __restrict__ cursor,
                            int* __restrict__ colIdx) {
    int i = blockIdx.x * blockDim.x + threadIdx.x;
    if (i >= nE) return;
    int p = atomicAdd(&cursor[ei[i]], 1);
    colIdx[p] = ei[nE + i];
}

// ---------------------------------------------------------------------------
// spmm via CSR on fp16 h: warp per row, fp32 accumulation (MLP-2).
// Each lane covers 4 cols = 8 bytes.
// ---------------------------------------------------------------------------
__global__ void __launch_bounds__(256) spmm_csr_kernel(
    const int* __restrict__ rowStart, const int* __restrict__ colIdx,
    const __half* __restrict__ hin, __half* __restrict__ hout, int n)
{
    int w = (blockIdx.x * 256 + threadIdx.x) >> 5;
    if (w >= n) return;
    int lane = threadIdx.x & 31;
    int s = rowStart[w];
    int e = rowStart[w + 1];

    float4 a0 = make_float4(0.f, 0.f, 0.f, 0.f);
    float4 a1 = make_float4(0.f, 0.f, 0.f, 0.f);
    int i = s;
    for (; i + 1 < e; i += 2) {
        int c0 = __ldg(&colIdx[i]);
        int c1 = __ldg(&colIdx[i + 1]);
        float4 v0 = ldh4(hin + (size_t)c0 * HIDDIM + lane * 4);
        float4 v1 = ldh4(hin + (size_t)c1 * HIDDIM + lane * 4);
        acc4(a0, v0); acc4(a1, v1);
    }
    if (i < e) {
        int c0 = __ldg(&colIdx[i]);
        float4 v0 = ldh4(hin + (size_t)c0 * HIDDIM + lane * 4);
        acc4(a0, v0);
    }
    acc4(a0, a1);
    sth4(hout + (size_t)w * HIDDIM + lane * 4, a0);
}

// ---------------------------------------------------------------------------
// Fused: spmm (fp16 gather) + W_out projection + log_softmax (MLP-2).
// ---------------------------------------------------------------------------
__global__ void __launch_bounds__(256) spmm_out_kernel(
    const int* __restrict__ rowStart, const int* __restrict__ colIdx,
    const __half* __restrict__ hin, const float* __restrict__ Wout,
    float* __restrict__ out, int n)
{
    __shared__ float W[HIDDIM * ODIM];
    for (int i = threadIdx.x; i < HIDDIM * ODIM; i += 256) W[i] = Wout[i];
    __syncthreads();

    int w = (blockIdx.x * 256 + threadIdx.x) >> 5;
    if (w >= n) return;
    int lane = threadIdx.x & 31;
    int s = rowStart[w];
    int e = rowStart[w + 1];

    float4 a0 = make_float4(0.f, 0.f, 0.f, 0.f);
    float4 a1 = make_float4(0.f, 0.f, 0.f, 0.f);
    int i = s;
    for (; i + 1 < e; i += 2) {
        int c0 = __ldg(&colIdx[i]);
        int c1 = __ldg(&colIdx[i + 1]);
        float4 v0 = ldh4(hin + (size_t)c0 * HIDDIM + lane * 4);
        float4 v1 = ldh4(hin + (size_t)c1 * HIDDIM + lane * 4);
        acc4(a0, v0); acc4(a1, v1);
    }
    if (i < e) {
        int c0 = __ldg(&colIdx[i]);
        float4 v0 = ldh4(hin + (size_t)c0 * HIDDIM + lane * 4);
        acc4(a0, v0);
    }
    acc4(a0, a1);
    float4 hv = a0;

    int i0 = lane * 4;
    float acc[ODIM];
#pragma unroll
    for (int o = 0; o < ODIM; o++) {
        float t = hv.x * W[(i0 + 0) * ODIM + o];
        t = fmaf(hv.y, W[(i0 + 1) * ODIM + o], t);
        t = fmaf(hv.z, W[(i0 + 2) * ODIM + o], t);
        t = fmaf(hv.w, W[(i0 + 3) * ODIM + o], t);
        acc[o] = t;
    }
#pragma unroll
    for (int off = 16; off > 0; off >>= 1)
#pragma unroll
        for (int o = 0; o < ODIM; o++)
            acc[o] += __shfl_xor_sync(0xffffffffu, acc[o], off);

    float m = acc[0];
#pragma unroll
    for (int o = 1; o < ODIM; o++) m = fmaxf(m, acc[o]);
    float sum = 0.f;
#pragma unroll
    for (int o = 0; o < ODIM; o++) sum += expf(acc[o] - m);
    float lse = m + logf(sum);
    if (lane < ODIM) out[(size_t)w * ODIM + lane] = acc[lane] - lse;
}

// ---------------------------------------------------------------------------
// tf32 mma.sync GEMM, cp.async 2-stage double-buffered pipeline.
//   CHEB=0: Cout = x @ Wt  (A = x fp32 via cp.async; raw bits -> mma.tf32)
//   CHEB=1: Cout = basis(tanh(h)) @ Ct + bias  (A = h fp16, ldg + basis -> STS)
// Output Cout is fp16.
// 8 warps as 2(m) x 4(n); warp tile 64x32; m16n8k8 atoms.
// ---------------------------------------------------------------------------
#define APITCH 36
#define BPITCH 136
#define ABYTES (128 * APITCH * 4)          // 18432
#define BBYTES (32 * BPITCH * 4)           // 17408
#define GEMM_SMEM (2 * (ABYTES + BBYTES))  // 71680

template <int CHEB>
__global__ void __launch_bounds__(256) gemm_mma(
    const void* __restrict__ Ain, const uint32_t* __restrict__ B,
    const float* __restrict__ bias, __half* __restrict__ Cout, int nRows)
{
    constexpr int KW     = CHEB ? 24 : 32;   // k-cols per chunk
    constexpr int NCH    = 16;
    constexpr int KSTEPS = CHEB ? 3 : 4;
    constexpr int BITER  = CHEB ? 3 : 4;     // B fill iterations

    extern __shared__ char smem[];
    const uint32_t sb = smem_u32(smem);

    const int tid  = threadIdx.x;
    const int wid  = tid >> 5;
    const int lane = tid & 31;
    const int wm = wid >> 2;
    const int wn = wid & 3;
    const int g = lane >> 2;
    const int t = lane & 3;
    const int rowBase = blockIdx.x * 128;

    const float*  Af = (const float*)Ain;    // mode0
    const __half* Ah = (const __half*)Ain;   // cheb

    float acc[4][4][4];
#pragma unroll
    for (int mf = 0; mf < 4; mf++)
#pragma unroll
        for (int nf = 0; nf < 4; nf++)
#pragma unroll
            for (int r = 0; r < 4; r++) acc[mf][nf][r] = 0.f;

    float aH[4];   // CHEB: staged h values (4 regs only)

    // ---- async issue of chunk c into buffer c&1 ----
    auto issue = [&](int c) {
        const int buf = c & 1;
        const uint32_t aBase = sb + buf * ABYTES;
        const uint32_t bBase = sb + 2 * ABYTES + buf * BBYTES;
        if (!CHEB) {
#pragma unroll
            for (int j = 0; j < 4; j++) {
                int pos = tid + j * 256;
                int row = pos >> 3, kq = pos & 7;
                int kk = c * 32 + kq * 4;
                int rg = rowBase + row; if (rg >= nRows) rg = nRows - 1;
                int sbytes = (KIN - kk) * 4;
                sbytes = sbytes < 0 ? 0 : (sbytes > 16 ? 16 : sbytes);
                cp16(aBase + (row * APITCH + kq * 4) * 4,
                     Af + (size_t)rg * KIN + kk, sbytes);
            }
        }
#pragma unroll
        for (int j = 0; j < BITER; j++) {
            int pos = tid + j * 256;
            int k = pos >> 5, nq = pos & 31;
            cp16(bBase + (k * BPITCH + nq * 4) * 4,
                 B + (size_t)(c * KW + k) * HIDDIM + nq * 4, 16);
        }
        CP_COMMIT();
    };
    auto ldgA = [&](int c) {
        if (CHEB) {
#pragma unroll
            for (int j = 0; j < 4; j++) {
                int pos = tid + j * 256;
                int row = pos >> 3, il = pos & 7;
                int rg = rowBase + row; if (rg >= nRows) rg = nRows - 1;
                aH[j] = __half2float(Ah[(size_t)rg * HIDDIM + c * 8 + il]);
            }
        }
    };

    issue(0);
    ldgA(0);

    for (int c = 0; c < NCH; c++) {
        const int buf = c & 1;
        uint32_t* As = (uint32_t*)(smem + buf * ABYTES);
        uint32_t* Bs = (uint32_t*)(smem + 2 * ABYTES + buf * BBYTES);

        if (CHEB) {
            // compute basis for chunk c, store fp32 bits (HW truncates)
#pragma unroll
            for (int j = 0; j < 4; j++) {
                int pos = tid + j * 256;
                int row = pos >> 3, il = pos & 7;
                float tv = tanh_fast(aH[j]);
                float T2 = fmaf(2.f * tv, tv, -1.f);
                float T3 = fmaf(2.f * tv, T2, -tv);
                uint32_t* p = &As[row * APITCH + il * 3];
                p[0] = __float_as_uint(tv);
                p[1] = __float_as_uint(T2);
                p[2] = __float_as_uint(T3);
            }
        }

        if (c + 1 < NCH) {
            issue(c + 1);      // into buffer (c+1)&1 — free since MMA c-1 synced
            ldgA(c + 1);       // h loads overlap wait + MMA below
            CP_WAIT1();        // chunk c's group complete
        } else {
            CP_WAIT0();
        }
        __syncthreads();

        // ---- KSTEPS x m16n8k8 ----
#pragma unroll
        for (int ks = 0; ks < KSTEPS; ks++) {
            const int kk = ks * 8;
            uint32_t a[4][4], b[4][2];
#pragma unroll
            for (int mf = 0; mf < 4; mf++) {
                int mb = wm * 64 + mf * 16;
                a[mf][0] = As[(mb + g)     * APITCH + kk + t];
                a[mf][1] = As[(mb + g + 8) * APITCH + kk + t];
                a[mf][2] = As[(mb + g)     * APITCH + kk + t + 4];
                a[mf][3] = As[(mb + g + 8) * APITCH + kk + t + 4];
            }
#pragma unroll
            for (int nf = 0; nf < 4; nf++) {
                int nb = wn * 32 + nf * 8;
                b[nf][0] = Bs[(kk + t)     * BPITCH + nb + g];
                b[nf][1] = Bs[(kk + t + 4) * BPITCH + nb + g];
            }
#pragma unroll
            for (int mf = 0; mf < 4; mf++)
#pragma unroll
                for (int nf = 0; nf < 4; nf++)
                    mma_tf32_16n8k8(acc[mf][nf], a[mf], b[nf]);
        }
        __syncthreads();       // MMA reads done before this buffer is refilled
    }

    // ---- epilogue: fp16 store (bias only in CHEB mode) ----
#pragma unroll
    for (int mf = 0; mf < 4; mf++) {
        int row0 = rowBase + wm * 64 + mf * 16 + g;
#pragma unroll
        for (int nf = 0; nf < 4; nf++) {
            int col = wn * 32 + nf * 8 + t * 2;
            float b0 = 0.f, b1 = 0.f;
            if (CHEB) { b0 = __ldg(&bias[col]); b1 = __ldg(&bias[col + 1]); }
            if (row0 < nRows) {
                __half2 hv = __floats2half2_rn(acc[mf][nf][0] + b0,
                                               acc[mf][nf][1] + b1);
                *(__half2*)&Cout[(size_t)row0 * HIDDIM + col] = hv;
            }
            if (row0 + 8 < nRows) {
                __half2 hv = __floats2half2_rn(acc[mf][nf][2] + b0,
                                               acc[mf][nf][3] + b1);
                *(__half2*)&Cout[(size_t)(row0 + 8) * HIDDIM + col] = hv;
            }
        }
    }
}

// ---------------------------------------------------------------------------
extern "C" void kernel_launch(void* const* d_in, const int* in_sizes, int n_in,
                              void* d_out, int out_size)
{
    const float* x    = (const float*)d_in[0];
    const int*   ei   = (const int*)d_in[1];
    const float* Win  = (const float*)d_in[2];
    const float* cc   = (const float*)d_in[3];
    const float* Wout = (const float*)d_in[4];
    float* out = (float*)d_out;

    const int nE    = in_sizes[1] / 2;
    const int nRows = NNODES;

    __half *h0, *h1;
    float *bias;
    uint32_t *Wt, *Ct;
    int *deg, *rowStart, *cursor, *colIdx;
    cudaGetSymbolAddress((void**)&h0, g_h0);
    cudaGetSymbolAddress((void**)&h1, g_h1);
    cudaGetSymbolAddress((void**)&Wt, g_Wt);
    cudaGetSymbolAddress((void**)&Ct, g_Ct);
    cudaGetSymbolAddress((void**)&bias, g_bias);
    cudaGetSymbolAddress((void**)&deg,      g_deg);
    cudaGetSymbolAddress((void**)&rowStart, g_rowStart);
    cudaGetSymbolAddress((void**)&cursor,   g_cursor);
    cudaGetSymbolAddress((void**)&colIdx,   g_colIdx);

    static bool attrDone = false;
    if (!attrDone) {
        cudaFuncSetAttribute(gemm_mma<0>,
            cudaFuncAttributeMaxDynamicSharedMemorySize, GEMM_SMEM);
        cudaFuncSetAttribute(gemm_mma<1>,
            cudaFuncAttributeMaxDynamicSharedMemorySize, GEMM_SMEM);
        attrDone = true;
    }

    const int gemmBlocks = (nRows + 127) / 128;          // 782
    const int eBlocks    = (nE + 255) / 256;
    const int spmmBlocks = (nRows * 32 + 255) / 256;
    const int prepElems  = KPAD * HIDDIM + 2 * KCH * HIDDIM;

    // Single stream; gemm_mma<0> at profiled position 4.
    zero_deg_kernel<<<(nRows + 255) / 256, 256>>>(deg, nRows);          // 1
    count_kernel<<<eBlocks, 256>>>(ei, nE, deg);                        // 2
    prep_kernel<<<(prepElems + 255) / 256, 256>>>(Win, cc);             // 3
    gemm_mma<0><<<gemmBlocks, 256, GEMM_SMEM>>>(x, Wt, nullptr, h0, nRows); // 4
    scan_kernel<<<1, 1024>>>(deg, rowStart, cursor, nRows);             // 5
    fill_kernel<<<eBlocks, 256>>>(ei, nE, cursor, colIdx);              // 6
    bias_kernel<<<1, 256>>>(cc);                                        // 7

    // h1 = A h0
    spmm_csr_kernel<<<spmmBlocks, 256>>>(rowStart, colIdx, h0, h1, nRows);
    // h0 = cheb(h1; C0)
    gemm_mma<1><<<gemmBlocks, 256, GEMM_SMEM>>>(h1, Ct, bias, h0, nRows);
    spmm_csr_kernel<<<spmmBlocks, 256>>>(rowStart, colIdx, h0, h1, nRows);
    // h0 = cheb(h1; C1)
    gemm_mma<1><<<gemmBlocks, 256, GEMM_SMEM>>>(h1, Ct + KCH * HIDDIM,
                                                bias + HIDDIM, h0, nRows);
    // fused: spmm + W_out + log_softmax
    spmm_out_kernel<<<spmmBlocks, 256>>>(rowStart, colIdx, h0, Wout, out, nRows);
}